// round 16
// baseline (speedup 1.0000x reference)
#include <cuda_runtime.h>
#include <cuda_fp16.h>
#include <math.h>
#include <stdint.h>

// Problem dims
#define DQ    2048
#define RQ    1024
#define MQ    128
#define EQ    64
#define TQ    32768
#define PADA  68

// k3: 128-token CTA, warp tile 32x64, fp16x3 m16n8k16, split-K=2.
// Warp-autonomous: per-warp A staging (cp.async + syncwarp, NO CTA barriers),
// B fragments via L1-cached LDG. 4-stage ring, 3-chunk lookahead.
#define KC        16
#define NST       4
#define KSPLIT    2
#define KHALF     (DQ / KSPLIT)              // 1024
#define NCH       (KHALF / KC)               // 64
#define SAF       24                         // floats per staged A row
#define ST_BYTES  (128 * SAF * 4)            // 12288
#define K3_SMEM_BYTES (NST * ST_BYTES)       // 49152

// ---------------- scratch ----------------
__device__ float  g_remb[EQ * RQ];
__device__ float  g_rembT[RQ * EQ];
__device__ float  g_partialT[8][EQ * DQ];   // [e][d] fp32
__device__ __half g_BhT[EQ * DQ];           // fp16-hi of W_combT [e][d]
__device__ __half g_BlT[EQ * DQ];           // fp16-lo
__device__ float  g_biasP[4][EQ];
__device__ float  g_bias[EQ];
__device__ float  g_plog[KSPLIT * TQ * EQ]; // split-K partial logits (16.8 MB)

__device__ __forceinline__ float mask11(float x) {   // keep 11 significand bits (fp16-exact)
    return __uint_as_float(__float_as_uint(x) & 0xFFFFE000u);
}
__device__ __forceinline__ uint32_t pack_h2(float lo, float hi) {
    __half2 h = __floats2half2_rn(lo, hi);
    return *reinterpret_cast<uint32_t*>(&h);
}
__device__ __forceinline__ uint32_t smem_u32(const void* p) {
    uint32_t a;
    asm("{ .reg .u64 t; cvta.to.shared.u64 t, %1; cvt.u32.u64 %0, t; }" : "=r"(a) : "l"(p));
    return a;
}
__device__ __forceinline__ void cpa16(uint32_t s, const void* g) {
    asm volatile("cp.async.cg.shared.global [%0], [%1], 16;" :: "r"(s), "l"(g));
}
#define CPA_COMMIT() asm volatile("cp.async.commit_group;" ::: "memory")
#define CPA_WAIT2()  asm volatile("cp.async.wait_group 2;" ::: "memory")
#define CPA_WAIT0()  asm volatile("cp.async.wait_group 0;" ::: "memory")

// m16n8k16 fp16 mma, f32 accum, D += A*B (row.col)
__device__ __forceinline__ void mma16(float* d, const uint32_t* a, uint32_t b0, uint32_t b1) {
    asm volatile(
        "mma.sync.aligned.m16n8k16.row.col.f32.f16.f16.f32 "
        "{%0,%1,%2,%3}, {%4,%5,%6,%7}, {%8,%9}, {%0,%1,%2,%3};"
        : "+f"(d[0]), "+f"(d[1]), "+f"(d[2]), "+f"(d[3])
        : "r"(a[0]), "r"(a[1]), "r"(a[2]), "r"(a[3]), "r"(b0), "r"(b1));
}

// ---------------------------------------------------------------------------
// K1: rkhs_emb[e][r] = sum_m emb[e][m]*W_exp[r][m] + b_exp[r], grid (EQ, 4).
// ---------------------------------------------------------------------------
__global__ void k1_remb(const float* __restrict__ W_exp,
                        const float* __restrict__ b_exp,
                        const float* __restrict__ emb,
                        const float* __restrict__ b_hid) {
    __shared__ float4 s_emb[MQ / 4];
    __shared__ float  red[8];
    const int e    = blockIdx.x;
    const int q    = blockIdx.y;
    const int tid  = threadIdx.x;
    const int w    = tid >> 5;
    const int lane = tid & 31;
    if (tid < MQ / 4) s_emb[tid] = reinterpret_cast<const float4*>(emb)[e * (MQ / 4) + tid];
    __syncthreads();
    const float4 ev = s_emb[lane];
    float bacc = 0.f;
#pragma unroll 4
    for (int i = 0; i < 32; i++) {
        const int r = q * 256 + w * 32 + i;
        float4 wv = reinterpret_cast<const float4*>(W_exp)[r * (MQ / 4) + lane];
        float p = wv.x * ev.x + wv.y * ev.y + wv.z * ev.z + wv.w * ev.w;
        p += __shfl_xor_sync(0xffffffffu, p, 16);
        p += __shfl_xor_sync(0xffffffffu, p, 8);
        p += __shfl_xor_sync(0xffffffffu, p, 4);
        p += __shfl_xor_sync(0xffffffffu, p, 2);
        p += __shfl_xor_sync(0xffffffffu, p, 1);
        if (lane == 0) {
            float v = p + b_exp[r];
            g_remb[e * RQ + r]  = v;
            g_rembT[r * EQ + e] = v;
            bacc += b_hid[r] * v;
        }
    }
    if (lane == 0) red[w] = bacc;
    __syncthreads();
    if (tid == 0) {
        float s = 0.f;
#pragma unroll
        for (int i = 0; i < 8; i++) s += red[i];
        g_biasP[q][e] = s;
    }
}

// ---------------------------------------------------------------------------
// K2: split-K GEMM -> partials of W_combT[e][d]
// ---------------------------------------------------------------------------
__global__ __launch_bounds__(256) void k2_part(const float* __restrict__ W_hid) {
    __shared__ float sW[16 * PADA];
    __shared__ float sR[16 * 64];
    const int tid = threadIdx.x;
    const int d0  = blockIdx.x * 64;
    const int r0  = blockIdx.y * 128;
    const int tm  = tid >> 4;
    const int tn  = tid & 15;
    const int rr  = tid >> 4;
    const int dq  = tid & 15;

    float acc[4][4];
#pragma unroll
    for (int i = 0; i < 4; i++)
#pragma unroll
        for (int j = 0; j < 4; j++) acc[i][j] = 0.f;

    const float4* RT4 = reinterpret_cast<const float4*>(g_rembT);

    for (int rk = 0; rk < 128; rk += 16) {
        *reinterpret_cast<float4*>(&sW[rr * PADA + dq * 4]) =
            *reinterpret_cast<const float4*>(&W_hid[(size_t)(r0 + rk + rr) * DQ + d0 + dq * 4]);
        *reinterpret_cast<float4*>(&sR[tid * 4]) = RT4[(size_t)(r0 + rk) * (EQ / 4) + tid];
        __syncthreads();
#pragma unroll
        for (int k = 0; k < 16; k++) {
            float4 a = *reinterpret_cast<const float4*>(&sW[k * PADA + tm * 4]);
            float4 b = *reinterpret_cast<const float4*>(&sR[k * 64 + tn * 4]);
            acc[0][0] += a.x * b.x; acc[0][1] += a.x * b.y; acc[0][2] += a.x * b.z; acc[0][3] += a.x * b.w;
            acc[1][0] += a.y * b.x; acc[1][1] += a.y * b.y; acc[1][2] += a.y * b.z; acc[1][3] += a.y * b.w;
            acc[2][0] += a.z * b.x; acc[2][1] += a.z * b.y; acc[2][2] += a.z * b.z; acc[2][3] += a.z * b.w;
            acc[3][0] += a.w * b.x; acc[3][1] += a.w * b.y; acc[3][2] += a.w * b.z; acc[3][3] += a.w * b.w;
        }
        __syncthreads();
    }
    float* dst = &g_partialT[blockIdx.y][0];
#pragma unroll
    for (int i = 0; i < 4; i++)
#pragma unroll
        for (int j = 0; j < 4; j++)
            dst[(size_t)(tn * 4 + j) * DQ + d0 + tm * 4 + i] = acc[i][j];
}

// K2r: reduce partials -> fp16 hi/lo; block 0 also reduces bias partials.
__global__ void k2_reduce() {
    const int i = blockIdx.x * 256 + threadIdx.x;
    float4 s = make_float4(0.f, 0.f, 0.f, 0.f);
#pragma unroll
    for (int p = 0; p < 8; p++) {
        float4 v = reinterpret_cast<const float4*>(&g_partialT[p][0])[i];
        s.x += v.x; s.y += v.y; s.z += v.z; s.w += v.w;
    }
    float hx = mask11(s.x), hy = mask11(s.y), hz = mask11(s.z), hw = mask11(s.w);
    reinterpret_cast<uint2*>(g_BhT)[i] = make_uint2(pack_h2(hx, hy), pack_h2(hz, hw));
    reinterpret_cast<uint2*>(g_BlT)[i] = make_uint2(pack_h2(s.x - hx, s.y - hy),
                                                   pack_h2(s.z - hz, s.w - hw));
    if (blockIdx.x == 0 && threadIdx.x < EQ) {
        const int e = threadIdx.x;
        g_bias[e] = (g_biasP[0][e] + g_biasP[1][e]) + (g_biasP[2][e] + g_biasP[3][e]);
    }
}

// ---------------------------------------------------------------------------
// K3a: warp-autonomous fp16x3 mma.sync GEMM partials.
// CTA = 128 tok x 64 exp x K-half; warp w owns rows [w*32, w*32+32).
// Per-warp cp.async A staging, B frags via L1-cached LDG. No CTA barriers.
// ---------------------------------------------------------------------------
__global__ __launch_bounds__(128, 4) void k3_mma(const float* __restrict__ input) {
    extern __shared__ char smc[];
    const int tid  = threadIdx.x;
    const int w    = tid >> 5;
    const int lane = tid & 31;
    const int g    = lane >> 2;
    const int c    = lane & 3;
    const int tok0 = blockIdx.x * 128;
    const int kb   = blockIdx.y * KHALF;

    float acc[2][8][4];
#pragma unroll
    for (int i = 0; i < 2; i++)
#pragma unroll
        for (int j = 0; j < 8; j++)
#pragma unroll
            for (int q2 = 0; q2 < 4; q2++) acc[i][j][q2] = 0.f;

    // per-warp A staging: lane stages rows w*32 + u*8 + (lane>>2), 16B seg lane&3
    const int srow = w * 32 + (lane >> 2);
    const int aj   = lane & 3;
    const uint32_t stg_u = smem_u32(smc);

    const __half* __restrict__ BhP = g_BhT + kb;
    const __half* __restrict__ BlP = g_BlT + kb;

    auto issueA = [&](int ch, int slot) {
        const uint32_t st = stg_u + slot * ST_BYTES;
        const int k0 = kb + ch * KC;
#pragma unroll
        for (int u = 0; u < 4; u++) {
            int row = srow + u * 8;
            cpa16(st + row * (SAF * 4) + aj * 16,
                  input + (size_t)(tok0 + row) * DQ + k0 + aj * 4);
        }
    };

    issueA(0, 0); CPA_COMMIT();
    issueA(1, 1); CPA_COMMIT();
    issueA(2, 2); CPA_COMMIT();

    int slot = 0;
    for (int ch = 0; ch < NCH; ch++) {
        CPA_WAIT2();        // own groups: chunk ch complete (ch+1, ch+2 pending)
        __syncwarp();       // cross-lane visibility within the warp

        const float* Af = reinterpret_cast<const float*>(smc + slot * ST_BYTES);
        const int kc0 = ch * KC;

        // A fragments: LDS.64 fp32 pairs -> split hi/lo in registers
        uint32_t ahf[2][4], alf[2][4];
#pragma unroll
        for (int i = 0; i < 2; i++) {
            const int rb = w * 32 + i * 16 + g;
#pragma unroll
            for (int q2 = 0; q2 < 4; q2++) {
                const int row = (q2 & 1) ? rb + 8 : rb;
                const int kk  = 2 * c + ((q2 >> 1) ? 8 : 0);
                float2 v = *reinterpret_cast<const float2*>(&Af[row * SAF + kk]);
                float hx = mask11(v.x), hy = mask11(v.y);
                ahf[i][q2] = pack_h2(hx, hy);
                alf[i][q2] = pack_h2(v.x - hx, v.y - hy);
            }
        }

        // pass 1: hi*hi — B hi frags via LDG (L1-resident), cached for pass 3
        uint32_t bhf[8][2];
#pragma unroll
        for (int j = 0; j < 8; j++) {
            const size_t eoff = (size_t)(j * 8 + g) * DQ + kc0 + 2 * c;
            bhf[j][0] = *reinterpret_cast<const uint32_t*>(&BhP[eoff]);
            bhf[j][1] = *reinterpret_cast<const uint32_t*>(&BhP[eoff + 8]);
            mma16(acc[0][j], ahf[0], bhf[j][0], bhf[j][1]);
            mma16(acc[1][j], ahf[1], bhf[j][0], bhf[j][1]);
        }
        // pass 2: hi*lo
#pragma unroll
        for (int j = 0; j < 8; j++) {
            const size_t eoff = (size_t)(j * 8 + g) * DQ + kc0 + 2 * c;
            uint32_t b0 = *reinterpret_cast<const uint32_t*>(&BlP[eoff]);
            uint32_t b1 = *reinterpret_cast<const uint32_t*>(&BlP[eoff + 8]);
            mma16(acc[0][j], ahf[0], b0, b1);
            mma16(acc[1][j], ahf[1], b0, b1);
        }
        // pass 3: lo*hi (reuse cached Bh)
#pragma unroll
        for (int j = 0; j < 8; j++) {
            mma16(acc[0][j], alf[0], bhf[j][0], bhf[j][1]);
            mma16(acc[1][j], alf[1], bhf[j][0], bhf[j][1]);
        }

        // prefetch chunk ch+3 into slot (ch-1)%NST — this warp is past it
        if (ch + 3 < NCH) {
            int ns = slot + 3; if (ns >= NST) ns -= NST;
            issueA(ch + 3, ns);
        }
        CPA_COMMIT();

        if (++slot == NST) slot = 0;
    }
    CPA_WAIT0();

    // ---- epilogue: raw fp32 partials -> g_plog[ks][tok][e] via STG.64 ----
    float* dst = g_plog + (size_t)blockIdx.y * TQ * EQ;
#pragma unroll
    for (int i = 0; i < 2; i++) {
        const int r0 = tok0 + w * 32 + i * 16 + g;
#pragma unroll
        for (int j = 0; j < 8; j++) {
            const int col = j * 8 + 2 * c;
            *reinterpret_cast<float2*>(&dst[(size_t)r0 * EQ + col]) =
                make_float2(acc[i][j][0], acc[i][j][1]);
            *reinterpret_cast<float2*>(&dst[(size_t)(r0 + 8) * EQ + col]) =
                make_float2(acc[i][j][2], acc[i][j][3]);
        }
    }
}

// ---------------------------------------------------------------------------
// K3r: sum the two K-half partials + bias, top-2 + renormalized softmax.
// ---------------------------------------------------------------------------
__global__ __launch_bounds__(128) void k3_red(float* __restrict__ out_idx,
                                              float* __restrict__ out_w,
                                              float* __restrict__ aux_ptr) {
    __shared__ float sb[EQ];
    const int tid = threadIdx.x;
    const int t   = blockIdx.x * 128 + tid;
    if (tid < EQ) sb[tid] = g_bias[tid];
    __syncthreads();

    const float4* p0 = reinterpret_cast<const float4*>(g_plog + (size_t)t * EQ);
    const float4* p1 = reinterpret_cast<const float4*>(g_plog + (size_t)(TQ + t) * EQ);

    float best = -INFINITY, second = -INFINITY;
    int bi = 0, si = 0;
#pragma unroll
    for (int i = 0; i < EQ / 4; i++) {
        float4 a = p0[i];
        float4 b = p1[i];
        float v[4];
        v[0] = a.x + b.x + sb[4 * i + 0];
        v[1] = a.y + b.y + sb[4 * i + 1];
        v[2] = a.z + b.z + sb[4 * i + 2];
        v[3] = a.w + b.w + sb[4 * i + 3];
#pragma unroll
        for (int q = 0; q < 4; q++) {
            const int e = 4 * i + q;
            if (v[q] > best)        { second = best; si = bi; best = v[q]; bi = e; }
            else if (v[q] > second) { second = v[q]; si = e; }
        }
    }
    float es  = expf(second - best);
    float inv = 1.f / (1.f + es);
    out_idx[t * 2 + 0] = (float)bi;
    out_idx[t * 2 + 1] = (float)si;
    out_w[t * 2 + 0]   = inv;
    out_w[t * 2 + 1]   = es * inv;

    if (blockIdx.x == 0 && tid == 0 && aux_ptr != nullptr) *aux_ptr = 64.0f;
}

// ---------------------------------------------------------------------------
extern "C" void kernel_launch(void* const* d_in, const int* in_sizes, int n_in,
                              void* d_out, int out_size) {
    const float* input = (const float*)d_in[0];
    const float* W_hid = (const float*)d_in[1];
    const float* b_hid = (const float*)d_in[2];
    const float* W_exp = (const float*)d_in[3];
    const float* b_exp = (const float*)d_in[4];
    const float* emb   = (const float*)d_in[5];

    float* out     = (float*)d_out;
    float* out_idx = out;
    float* out_w   = out + 2 * TQ;
    float* aux     = (out_size > 4 * TQ) ? (out + (out_size - 1)) : nullptr;

    cudaFuncSetAttribute(k3_mma, cudaFuncAttributeMaxDynamicSharedMemorySize, K3_SMEM_BYTES);

    k1_remb<<<dim3(EQ, 4), 256>>>(W_exp, b_exp, emb, b_hid);
    k2_part<<<dim3(DQ / 64, 8), 256>>>(W_hid);
    k2_reduce<<<(EQ * DQ / 4) / 256, 256>>>();
    k3_mma<<<dim3(TQ / 128, KSPLIT), 128, K3_SMEM_BYTES>>>(input);
    k3_red<<<TQ / 128, 128>>>(out_idx, out_w, aux);
}

// round 17
// speedup vs baseline: 1.4442x; 1.4442x over previous
#include <cuda_runtime.h>
#include <cuda_fp16.h>
#include <math.h>
#include <stdint.h>

// Problem dims
#define DQ    2048
#define RQ    1024
#define MQ    128
#define EQ    64
#define TQ    32768
#define PADA  68

// k3: 128-token CTA, warp tile 32x64, fp16x3 m16n8k16, split-K=2.
// A: per-warp cp.async ring (NST=3, 2-chunk lookahead, no CTA sync).
// B: 4-chunk blocks in smem, double-buffered, ONE __syncthreads per block.
#define KC        16
#define NSTA      3
#define KSPLIT    2
#define KHALF     (DQ / KSPLIT)              // 1024
#define NCH       (KHALF / KC)               // 64
#define NBLK      (NCH / 4)                  // 16 B blocks of 64 k
#define SAF       24                         // floats per staged A row (all-32-bank)
#define A_ST_BYTES (128 * SAF * 4)           // 12288
#define B_ROW_H   72                         // halfs per B row (64 + 8 pad, all-32-bank)
#define B_HALF_BYTES (64 * B_ROW_H * 2)      // 9216 (hi or lo)
#define B_BLK_BYTES  (2 * B_HALF_BYTES)      // 18432
#define B_OFF     (NSTA * A_ST_BYTES)        // 36864
#define K3_SMEM_BYTES (B_OFF + 2 * B_BLK_BYTES)  // 73728

// ---------------- scratch ----------------
__device__ float  g_remb[EQ * RQ];
__device__ float  g_rembT[RQ * EQ];
__device__ float  g_partialT[8][EQ * DQ];   // [e][d] fp32
__device__ __half g_BhT[EQ * DQ];           // fp16-hi of W_combT [e][d]
__device__ __half g_BlT[EQ * DQ];           // fp16-lo
__device__ float  g_biasP[4][EQ];
__device__ float  g_bias[EQ];
__device__ float  g_plog[KSPLIT * TQ * EQ]; // split-K partial logits (16.8 MB)

__device__ __forceinline__ float mask11(float x) {   // keep 11 significand bits (fp16-exact)
    return __uint_as_float(__float_as_uint(x) & 0xFFFFE000u);
}
__device__ __forceinline__ uint32_t pack_h2(float lo, float hi) {
    __half2 h = __floats2half2_rn(lo, hi);
    return *reinterpret_cast<uint32_t*>(&h);
}
__device__ __forceinline__ uint32_t smem_u32(const void* p) {
    uint32_t a;
    asm("{ .reg .u64 t; cvta.to.shared.u64 t, %1; cvt.u32.u64 %0, t; }" : "=r"(a) : "l"(p));
    return a;
}
__device__ __forceinline__ void cpa16(uint32_t s, const void* g) {
    asm volatile("cp.async.cg.shared.global [%0], [%1], 16;" :: "r"(s), "l"(g));
}
#define CPA_COMMIT() asm volatile("cp.async.commit_group;" ::: "memory")
#define CPA_WAIT1()  asm volatile("cp.async.wait_group 1;" ::: "memory")
#define CPA_WAIT0()  asm volatile("cp.async.wait_group 0;" ::: "memory")

// m16n8k16 fp16 mma, f32 accum, D += A*B (row.col)
__device__ __forceinline__ void mma16(float* d, const uint32_t* a, uint32_t b0, uint32_t b1) {
    asm volatile(
        "mma.sync.aligned.m16n8k16.row.col.f32.f16.f16.f32 "
        "{%0,%1,%2,%3}, {%4,%5,%6,%7}, {%8,%9}, {%0,%1,%2,%3};"
        : "+f"(d[0]), "+f"(d[1]), "+f"(d[2]), "+f"(d[3])
        : "r"(a[0]), "r"(a[1]), "r"(a[2]), "r"(a[3]), "r"(b0), "r"(b1));
}

// ---------------------------------------------------------------------------
// K1: rkhs_emb[e][r] = sum_m emb[e][m]*W_exp[r][m] + b_exp[r], grid (EQ, 4).
// ---------------------------------------------------------------------------
__global__ void k1_remb(const float* __restrict__ W_exp,
                        const float* __restrict__ b_exp,
                        const float* __restrict__ emb,
                        const float* __restrict__ b_hid) {
    __shared__ float4 s_emb[MQ / 4];
    __shared__ float  red[8];
    const int e    = blockIdx.x;
    const int q    = blockIdx.y;
    const int tid  = threadIdx.x;
    const int w    = tid >> 5;
    const int lane = tid & 31;
    if (tid < MQ / 4) s_emb[tid] = reinterpret_cast<const float4*>(emb)[e * (MQ / 4) + tid];
    __syncthreads();
    const float4 ev = s_emb[lane];
    float bacc = 0.f;
#pragma unroll 4
    for (int i = 0; i < 32; i++) {
        const int r = q * 256 + w * 32 + i;
        float4 wv = reinterpret_cast<const float4*>(W_exp)[r * (MQ / 4) + lane];
        float p = wv.x * ev.x + wv.y * ev.y + wv.z * ev.z + wv.w * ev.w;
        p += __shfl_xor_sync(0xffffffffu, p, 16);
        p += __shfl_xor_sync(0xffffffffu, p, 8);
        p += __shfl_xor_sync(0xffffffffu, p, 4);
        p += __shfl_xor_sync(0xffffffffu, p, 2);
        p += __shfl_xor_sync(0xffffffffu, p, 1);
        if (lane == 0) {
            float v = p + b_exp[r];
            g_remb[e * RQ + r]  = v;
            g_rembT[r * EQ + e] = v;
            bacc += b_hid[r] * v;
        }
    }
    if (lane == 0) red[w] = bacc;
    __syncthreads();
    if (tid == 0) {
        float s = 0.f;
#pragma unroll
        for (int i = 0; i < 8; i++) s += red[i];
        g_biasP[q][e] = s;
    }
}

// ---------------------------------------------------------------------------
// K2: split-K GEMM -> partials of W_combT[e][d]
// ---------------------------------------------------------------------------
__global__ __launch_bounds__(256) void k2_part(const float* __restrict__ W_hid) {
    __shared__ float sW[16 * PADA];
    __shared__ float sR[16 * 64];
    const int tid = threadIdx.x;
    const int d0  = blockIdx.x * 64;
    const int r0  = blockIdx.y * 128;
    const int tm  = tid >> 4;
    const int tn  = tid & 15;
    const int rr  = tid >> 4;
    const int dq  = tid & 15;

    float acc[4][4];
#pragma unroll
    for (int i = 0; i < 4; i++)
#pragma unroll
        for (int j = 0; j < 4; j++) acc[i][j] = 0.f;

    const float4* RT4 = reinterpret_cast<const float4*>(g_rembT);

    for (int rk = 0; rk < 128; rk += 16) {
        *reinterpret_cast<float4*>(&sW[rr * PADA + dq * 4]) =
            *reinterpret_cast<const float4*>(&W_hid[(size_t)(r0 + rk + rr) * DQ + d0 + dq * 4]);
        *reinterpret_cast<float4*>(&sR[tid * 4]) = RT4[(size_t)(r0 + rk) * (EQ / 4) + tid];
        __syncthreads();
#pragma unroll
        for (int k = 0; k < 16; k++) {
            float4 a = *reinterpret_cast<const float4*>(&sW[k * PADA + tm * 4]);
            float4 b = *reinterpret_cast<const float4*>(&sR[k * 64 + tn * 4]);
            acc[0][0] += a.x * b.x; acc[0][1] += a.x * b.y; acc[0][2] += a.x * b.z; acc[0][3] += a.x * b.w;
            acc[1][0] += a.y * b.x; acc[1][1] += a.y * b.y; acc[1][2] += a.y * b.z; acc[1][3] += a.y * b.w;
            acc[2][0] += a.z * b.x; acc[2][1] += a.z * b.y; acc[2][2] += a.z * b.z; acc[2][3] += a.z * b.w;
            acc[3][0] += a.w * b.x; acc[3][1] += a.w * b.y; acc[3][2] += a.w * b.z; acc[3][3] += a.w * b.w;
        }
        __syncthreads();
    }
    float* dst = &g_partialT[blockIdx.y][0];
#pragma unroll
    for (int i = 0; i < 4; i++)
#pragma unroll
        for (int j = 0; j < 4; j++)
            dst[(size_t)(tn * 4 + j) * DQ + d0 + tm * 4 + i] = acc[i][j];
}

// K2r: reduce partials -> fp16 hi/lo; block 0 also reduces bias partials.
__global__ void k2_reduce() {
    const int i = blockIdx.x * 256 + threadIdx.x;
    float4 s = make_float4(0.f, 0.f, 0.f, 0.f);
#pragma unroll
    for (int p = 0; p < 8; p++) {
        float4 v = reinterpret_cast<const float4*>(&g_partialT[p][0])[i];
        s.x += v.x; s.y += v.y; s.z += v.z; s.w += v.w;
    }
    float hx = mask11(s.x), hy = mask11(s.y), hz = mask11(s.z), hw = mask11(s.w);
    reinterpret_cast<uint2*>(g_BhT)[i] = make_uint2(pack_h2(hx, hy), pack_h2(hz, hw));
    reinterpret_cast<uint2*>(g_BlT)[i] = make_uint2(pack_h2(s.x - hx, s.y - hy),
                                                   pack_h2(s.z - hz, s.w - hw));
    if (blockIdx.x == 0 && threadIdx.x < EQ) {
        const int e = threadIdx.x;
        g_bias[e] = (g_biasP[0][e] + g_biasP[1][e]) + (g_biasP[2][e] + g_biasP[3][e]);
    }
}

// ---------------------------------------------------------------------------
// K3a: hybrid fp16x3 mma.sync GEMM partials.
// A: per-warp cp.async ring (no CTA sync). B: 4-chunk smem blocks, double-
// buffered, one __syncthreads per block boundary (16 total).
// ---------------------------------------------------------------------------
__global__ __launch_bounds__(128, 3) void k3_mma(const float* __restrict__ input) {
    extern __shared__ char smc[];
    const int tid  = threadIdx.x;
    const int w    = tid >> 5;
    const int lane = tid & 31;
    const int g    = lane >> 2;
    const int c    = lane & 3;
    const int tok0 = blockIdx.x * 128;
    const int kb   = blockIdx.y * KHALF;

    float acc[2][8][4];
#pragma unroll
    for (int i = 0; i < 2; i++)
#pragma unroll
        for (int j = 0; j < 8; j++)
#pragma unroll
            for (int q2 = 0; q2 < 4; q2++) acc[i][j][q2] = 0.f;

    // A staging: lane stages rows srow + 8u, 16B seg aj (per-warp rows only)
    const int srow = w * 32 + (lane >> 2);
    const int aj   = lane & 3;
    // B staging: thread stages expert eb = tid>>1, half-row seg sb = tid&1
    const int eb = tid >> 1, sb = tid & 1;

    const uint32_t stg_u = smem_u32(smc);

    auto issueA = [&](int ch, int slot) {
        const uint32_t st = stg_u + slot * A_ST_BYTES;
        const int k0 = kb + ch * KC;
#pragma unroll
        for (int u = 0; u < 4; u++) {
            int row = srow + u * 8;
            cpa16(st + row * (SAF * 4) + aj * 16,
                  input + (size_t)(tok0 + row) * DQ + k0 + aj * 4);
        }
    };
    // stage B block blk (64 k) into slot bslot: hi rows then lo rows.
    auto issueB = [&](int blk, int bslot) {
        const uint32_t bh = stg_u + B_OFF + bslot * B_BLK_BYTES;
        const size_t src = (size_t)eb * DQ + kb + blk * 64 + sb * 32;
#pragma unroll
        for (int i = 0; i < 4; i++) {
            cpa16(bh + eb * (B_ROW_H * 2) + sb * 64 + i * 16, g_BhT + src + i * 8);
            cpa16(bh + B_HALF_BYTES + eb * (B_ROW_H * 2) + sb * 64 + i * 16,
                  g_BlT + src + i * 8);
        }
    };

    // prologue: G0 = {B block 0, A chunk 0}; G1 = {A chunk 1}
    issueB(0, 0); issueA(0, 0); CPA_COMMIT();
    issueA(1, 1); CPA_COMMIT();

    for (int ch = 0; ch < NCH; ch++) {
        CPA_WAIT1();        // completes all groups except the newest
        __syncwarp();
        if ((ch & 3) == 0) {
            __syncthreads();                  // publish B block ch/4; free old slot
            const int nb = (ch >> 2) + 1;
            if (nb < NBLK) issueB(nb, nb & 1);  // into this iteration's group
        }

        const float*  Af = reinterpret_cast<const float*>(smc + (ch % NSTA) * A_ST_BYTES);
        const __half* Bh = reinterpret_cast<const __half*>(
            smc + B_OFF + ((ch >> 2) & 1) * B_BLK_BYTES);
        const __half* Bl = Bh + B_HALF_BYTES / 2;
        const int kl = (ch & 3) * 16;         // local k within B block

        // A fragments: LDS.64 fp32 pairs -> split hi/lo in registers
        uint32_t ahf[2][4], alf[2][4];
#pragma unroll
        for (int i = 0; i < 2; i++) {
            const int rb = w * 32 + i * 16 + g;
#pragma unroll
            for (int q2 = 0; q2 < 4; q2++) {
                const int row = (q2 & 1) ? rb + 8 : rb;
                const int kk  = 2 * c + ((q2 >> 1) ? 8 : 0);
                float2 v = *reinterpret_cast<const float2*>(&Af[row * SAF + kk]);
                float hx = mask11(v.x), hy = mask11(v.y);
                ahf[i][q2] = pack_h2(hx, hy);
                alf[i][q2] = pack_h2(v.x - hx, v.y - hy);
            }
        }

        // pass 1: hi*hi — cache Bh fragments for pass 3
        uint32_t bhf[8][2];
#pragma unroll
        for (int j = 0; j < 8; j++) {
            const int eo = (j * 8 + g) * B_ROW_H + kl + 2 * c;
            bhf[j][0] = *reinterpret_cast<const uint32_t*>(&Bh[eo]);
            bhf[j][1] = *reinterpret_cast<const uint32_t*>(&Bh[eo + 8]);
            mma16(acc[0][j], ahf[0], bhf[j][0], bhf[j][1]);
            mma16(acc[1][j], ahf[1], bhf[j][0], bhf[j][1]);
        }
        // pass 2: hi*lo
#pragma unroll
        for (int j = 0; j < 8; j++) {
            const int eo = (j * 8 + g) * B_ROW_H + kl + 2 * c;
            uint32_t b0 = *reinterpret_cast<const uint32_t*>(&Bl[eo]);
            uint32_t b1 = *reinterpret_cast<const uint32_t*>(&Bl[eo + 8]);
            mma16(acc[0][j], ahf[0], b0, b1);
            mma16(acc[1][j], ahf[1], b0, b1);
        }
        // pass 3: lo*hi (reuse cached Bh)
#pragma unroll
        for (int j = 0; j < 8; j++) {
            mma16(acc[0][j], alf[0], bhf[j][0], bhf[j][1]);
            mma16(acc[1][j], alf[1], bhf[j][0], bhf[j][1]);
        }

        // per-warp A prefetch: chunk ch+2 into slot (ch+2)%3 (this warp done
        // with it — it held chunk ch-1). Always commit to keep group cadence.
        if (ch + 2 < NCH) issueA(ch + 2, (ch + 2) % NSTA);
        CPA_COMMIT();
    }
    CPA_WAIT0();

    // ---- epilogue: raw fp32 partials -> g_plog[ks][tok][e] via STG.64 ----
    float* dst = g_plog + (size_t)blockIdx.y * TQ * EQ;
#pragma unroll
    for (int i = 0; i < 2; i++) {
        const int r0 = tok0 + w * 32 + i * 16 + g;
#pragma unroll
        for (int j = 0; j < 8; j++) {
            const int col = j * 8 + 2 * c;
            *reinterpret_cast<float2*>(&dst[(size_t)r0 * EQ + col]) =
                make_float2(acc[i][j][0], acc[i][j][1]);
            *reinterpret_cast<float2*>(&dst[(size_t)(r0 + 8) * EQ + col]) =
                make_float2(acc[i][j][2], acc[i][j][3]);
        }
    }
}

// ---------------------------------------------------------------------------
// K3r: sum the two K-half partials + bias, top-2 + renormalized softmax.
// ---------------------------------------------------------------------------
__global__ __launch_bounds__(128) void k3_red(float* __restrict__ out_idx,
                                              float* __restrict__ out_w,
                                              float* __restrict__ aux_ptr) {
    __shared__ float sb[EQ];
    const int tid = threadIdx.x;
    const int t   = blockIdx.x * 128 + tid;
    if (tid < EQ) sb[tid] = g_bias[tid];
    __syncthreads();

    const float4* p0 = reinterpret_cast<const float4*>(g_plog + (size_t)t * EQ);
    const float4* p1 = reinterpret_cast<const float4*>(g_plog + (size_t)(TQ + t) * EQ);

    float best = -INFINITY, second = -INFINITY;
    int bi = 0, si = 0;
#pragma unroll
    for (int i = 0; i < EQ / 4; i++) {
        float4 a = p0[i];
        float4 b = p1[i];
        float v[4];
        v[0] = a.x + b.x + sb[4 * i + 0];
        v[1] = a.y + b.y + sb[4 * i + 1];
        v[2] = a.z + b.z + sb[4 * i + 2];
        v[3] = a.w + b.w + sb[4 * i + 3];
#pragma unroll
        for (int q = 0; q < 4; q++) {
            const int e = 4 * i + q;
            if (v[q] > best)        { second = best; si = bi; best = v[q]; bi = e; }
            else if (v[q] > second) { second = v[q]; si = e; }
        }
    }
    float es  = expf(second - best);
    float inv = 1.f / (1.f + es);
    out_idx[t * 2 + 0] = (float)bi;
    out_idx[t * 2 + 1] = (float)si;
    out_w[t * 2 + 0]   = inv;
    out_w[t * 2 + 1]   = es * inv;

    if (blockIdx.x == 0 && tid == 0 && aux_ptr != nullptr) *aux_ptr = 64.0f;
}

// ---------------------------------------------------------------------------
extern "C" void kernel_launch(void* const* d_in, const int* in_sizes, int n_in,
                              void* d_out, int out_size) {
    const float* input = (const float*)d_in[0];
    const float* W_hid = (const float*)d_in[1];
    const float* b_hid = (const float*)d_in[2];
    const float* W_exp = (const float*)d_in[3];
    const float* b_exp = (const float*)d_in[4];
    const float* emb   = (const float*)d_in[5];

    float* out     = (float*)d_out;
    float* out_idx = out;
    float* out_w   = out + 2 * TQ;
    float* aux     = (out_size > 4 * TQ) ? (out + (out_size - 1)) : nullptr;

    cudaFuncSetAttribute(k3_mma, cudaFuncAttributeMaxDynamicSharedMemorySize, K3_SMEM_BYTES);

    k1_remb<<<dim3(EQ, 4), 256>>>(W_exp, b_exp, emb, b_hid);
    k2_part<<<dim3(DQ / 64, 8), 256>>>(W_hid);
    k2_reduce<<<(EQ * DQ / 4) / 256, 256>>>();
    k3_mma<<<dim3(TQ / 128, KSPLIT), 128, K3_SMEM_BYTES>>>(input);
    k3_red<<<TQ / 128, 128>>>(out_idx, out_w, aux);
}